// round 8
// baseline (speedup 1.0000x reference)
#include <cuda_runtime.h>
#include <cstdint>

// Problem dims (fixed for this instance)
#define BQ 64
#define TQ 256
#define DQ 300
#define HQ 256      // hidden
#define KQ 37       // tags
#define MBQ (TQ*BQ) // 16384 rows (t*B + b)
#define CLSZ 8

typedef unsigned long long ull;

// ---------------- scratch (static device globals; no allocation) ----------------
__device__ float g_xgA[(size_t)MBQ * 1024];  // 64 MB
__device__ float g_xgB[(size_t)MBQ * 1024];  // 64 MB
__device__ float g_h0 [(size_t)MBQ * 512];   // 32 MB
__device__ float g_h1 [(size_t)MBQ * 512];   // 32 MB
__device__ float g_em [(size_t)MBQ * KQ];    // 2.4 MB
__device__ float g_llh[BQ];

// ---------------- helpers ----------------
__device__ __forceinline__ float sigf(float x)   { return 1.0f / (1.0f + __expf(-x)); }
__device__ __forceinline__ float tanh_f(float x) { return 2.0f / (1.0f + __expf(-2.0f * x)) - 1.0f; }

__device__ __forceinline__ ull ffma2(ull a, ull b, ull c) {
    ull d;
    asm("fma.rn.f32x2 %0, %1, %2, %3;" : "=l"(d) : "l"(a), "l"(b), "l"(c));
    return d;
}
__device__ __forceinline__ ull pk2(float lo, float hi) {
    ull r;
    asm("mov.b64 %0, {%1, %2};" : "=l"(r) : "f"(lo), "f"(hi));
    return r;
}
__device__ __forceinline__ float2 unpk2(ull v) {
    float2 r;
    asm("mov.b64 {%0, %1}, %2;" : "=f"(r.x), "=f"(r.y) : "l"(v));
    return r;
}
__device__ __forceinline__ uint32_t smem_u32(const void* p) {
    uint32_t a;
    asm("{ .reg .u64 t; cvta.to.shared.u64 t, %1; cvt.u32.u64 %0, t; }" : "=r"(a) : "l"(p));
    return a;
}

// ---------------- GEMM: C[M,N] = A(M,K) * Bw(N,K)^T + bias(N) ----------------
// 128x128 tile, 16-k, 256 threads, 8x8 microtile via FFMA2 (j-paired accumulators).
#define GBM 128
#define GBN 128
#define GBK 16

template <bool GATHER>
__global__ void __launch_bounds__(256)
gemm_nt_bias(const float* __restrict__ A, const int* __restrict__ textp,
             const float* __restrict__ Bw, const float* __restrict__ bias,
             float* __restrict__ C, int M, int N, int Kd, int lda)
{
    __shared__ float As[GBK * GBM];
    __shared__ float Bs[GBK * GBN];

    const int tid = threadIdx.x;
    const int m0  = blockIdx.y * GBM;
    const int n0  = blockIdx.x * GBN;
    const int tx  = tid & 15;
    const int ty  = tid >> 4;
    const int lrow = tid >> 1;
    const int lkv0 = (tid & 1) * 2;

    ull acc2[8][4];
    #pragma unroll
    for (int i = 0; i < 8; ++i)
        #pragma unroll
        for (int j = 0; j < 4; ++j) acc2[i][j] = 0ull;

    const float* arow_p;
    {
        const int m = m0 + lrow;
        if (GATHER) {
            const int bb = m & 63;
            const int tt = m >> 6;
            const int tok = textp[bb * TQ + tt];
            arow_p = A + (size_t)tok * lda;
        } else {
            arow_p = A + (size_t)m * lda;
        }
    }
    const int nrow = n0 + lrow;
    const float* brow_p = Bw + (size_t)nrow * Kd;
    const bool bvalid = nrow < N;

    const int Ktiles = (Kd + GBK - 1) / GBK;
    for (int kt = 0; kt < Ktiles; ++kt) {
        const int kb = kt * GBK;
        #pragma unroll
        for (int q = 0; q < 2; ++q) {
            const int kv = lkv0 + q;
            const int kg = kb + kv * 4;
            float4 va = make_float4(0.f, 0.f, 0.f, 0.f);
            float4 vb = make_float4(0.f, 0.f, 0.f, 0.f);
            if (kg + 3 < Kd) {
                va = *(const float4*)(arow_p + kg);
                if (bvalid) vb = *(const float4*)(brow_p + kg);
            }
            As[(kv * 4 + 0) * GBM + lrow] = va.x;
            As[(kv * 4 + 1) * GBM + lrow] = va.y;
            As[(kv * 4 + 2) * GBM + lrow] = va.z;
            As[(kv * 4 + 3) * GBM + lrow] = va.w;
            Bs[(kv * 4 + 0) * GBN + lrow] = vb.x;
            Bs[(kv * 4 + 1) * GBN + lrow] = vb.y;
            Bs[(kv * 4 + 2) * GBN + lrow] = vb.z;
            Bs[(kv * 4 + 3) * GBN + lrow] = vb.w;
        }
        __syncthreads();
        #pragma unroll
        for (int k = 0; k < GBK; ++k) {
            const float4 a0 = *(const float4*)&As[k * GBM + ty * 4];
            const float4 a1 = *(const float4*)&As[k * GBM + 64 + ty * 4];
            const ulonglong2 b0 = *(const ulonglong2*)&Bs[k * GBN + tx * 4];
            const ulonglong2 b1 = *(const ulonglong2*)&Bs[k * GBN + 64 + tx * 4];
            const ull bv2[4] = {b0.x, b0.y, b1.x, b1.y};
            const float av[8] = {a0.x, a0.y, a0.z, a0.w, a1.x, a1.y, a1.z, a1.w};
            #pragma unroll
            for (int i = 0; i < 8; ++i) {
                const ull av2 = pk2(av[i], av[i]);
                #pragma unroll
                for (int j = 0; j < 4; ++j)
                    acc2[i][j] = ffma2(av2, bv2[j], acc2[i][j]);
            }
        }
        __syncthreads();
    }
    #pragma unroll
    for (int i = 0; i < 8; ++i) {
        const int mi = (i < 4) ? (ty * 4 + i) : (64 + ty * 4 + (i - 4));
        const int m  = m0 + mi;
        #pragma unroll
        for (int j = 0; j < 4; ++j) {
            const float2 v = unpk2(acc2[i][j]);
            const int c0 = (j < 2) ? (tx * 4 + 2 * j) : (64 + tx * 4 + 2 * (j - 2));
            if (c0 + 0 + n0 < N) C[(size_t)m * N + n0 + c0 + 0] = v.x + bias[n0 + c0 + 0];
            if (c0 + 1 + n0 < N) C[(size_t)m * N + n0 + c0 + 1] = v.y + bias[n0 + c0 + 1];
        }
    }
}

// ---------------- cluster-based bidirectional LSTM scan ----------------
// grid = 128 CTAs = 16 clusters of 8. Cluster = (dir, batch-octet).
// CTA (rank r) owns units u0=r*32 .. +31 (all 4 gates) for its 8 batches.
// Whh slice (128 rows x 256) lives in REGISTERS (128 floats/thread).
// h exchanged inside the cluster via DSMEM push + cluster.sync (double buffer).
// Thread map: tid = ul*8 + ks  (ul: unit 0..31, ks: k-slice 0..7).
__global__ void __launch_bounds__(256) __cluster_dims__(CLSZ, 1, 1)
lstm_scan_cluster(const float* __restrict__ xgF, const float* __restrict__ xgBk,
                  const float* __restrict__ WhhF, const float* __restrict__ WhhB,
                  float* __restrict__ hout)
{
    __shared__ float hbuf[2][8][256];   // 16KB: [buf][batch][unit]
    __shared__ float stage[256];        // this CTA's h slice: [batch][ul]

    uint32_t rank;
    asm("mov.u32 %0, %%cluster_ctarank;" : "=r"(rank));
    const int cid = blockIdx.x >> 3;          // cluster id 0..15
    const int dir = cid >> 3;                 // 0 fwd, 1 bwd
    const int b0  = (cid & 7) * 8;            // batch octet
    const int u0  = (int)rank * 32;
    const int tid = threadIdx.x;
    const int ul  = tid >> 3;                 // 0..31
    const int ks  = tid & 7;                  // 0..7
    const int dof = dir ? 256 : 0;

    const float* xg  = dir ? xgBk : xgF;
    const float* Whh = dir ? WhhB : WhhF;

    // ---- load Whh slice into registers: w[g][q] is float4 (as 2x f32x2) ----
    // row = g*256 + u0 + ul ; float4 col index kv = ks + q*8 (k = kv*4..kv*4+3)
    ull w[4][8][2];
    #pragma unroll
    for (int g = 0; g < 4; ++g)
        #pragma unroll
        for (int q = 0; q < 8; ++q) {
            const int kv = ks + q * 8;
            const ulonglong2 v = *(const ulonglong2*)&Whh[(size_t)(g * 256 + u0 + ul) * 256 + kv * 4];
            w[g][q][0] = v.x;
            w[g][q][1] = v.y;
        }

    const uint32_t hb_addr = smem_u32(&hbuf[0][0][0]);
    const bool epi = (ks == 0);

    float cc[8];
    #pragma unroll
    for (int i = 0; i < 8; ++i) cc[i] = 0.0f;

    int p = 0;
    for (int s = 0; s < TQ; ++s) {
        const int t = dir ? (TQ - 1 - s) : s;

        // prefetch xg for this step (epilogue lanes only; latency hides under compute)
        float xv[8][4];
        if (epi) {
            const float* xgt = xg + ((size_t)t * BQ + b0) * 1024;
            #pragma unroll
            for (int b = 0; b < 8; ++b)
                #pragma unroll
                for (int g = 0; g < 4; ++g)
                    xv[b][g] = __ldg(xgt + (size_t)b * 1024 + g * 256 + u0 + ul);
        }

        #pragma unroll
        for (int pass = 0; pass < 2; ++pass) {
            ull acc2[4][4];
            #pragma unroll
            for (int bi = 0; bi < 4; ++bi)
                #pragma unroll
                for (int g = 0; g < 4; ++g) acc2[bi][g] = 0ull;

            if (s > 0) {
                const float* hp = &hbuf[p][pass * 4][0];
                #pragma unroll
                for (int q = 0; q < 8; ++q) {
                    const int kv = ks + q * 8;
                    ulonglong2 hv[4];
                    #pragma unroll
                    for (int bi = 0; bi < 4; ++bi)
                        hv[bi] = *(const ulonglong2*)(hp + bi * 256 + kv * 4);
                    #pragma unroll
                    for (int bi = 0; bi < 4; ++bi) {
                        acc2[bi][0] = ffma2(hv[bi].x, w[0][q][0], acc2[bi][0]);
                        acc2[bi][0] = ffma2(hv[bi].y, w[0][q][1], acc2[bi][0]);
                        acc2[bi][1] = ffma2(hv[bi].x, w[1][q][0], acc2[bi][1]);
                        acc2[bi][1] = ffma2(hv[bi].y, w[1][q][1], acc2[bi][1]);
                        acc2[bi][2] = ffma2(hv[bi].x, w[2][q][0], acc2[bi][2]);
                        acc2[bi][2] = ffma2(hv[bi].y, w[2][q][1], acc2[bi][2]);
                        acc2[bi][3] = ffma2(hv[bi].x, w[3][q][0], acc2[bi][3]);
                        acc2[bi][3] = ffma2(hv[bi].y, w[3][q][1], acc2[bi][3]);
                    }
                }
            }

            // reduce f32x2 halves + ks lanes (xor 1,2,4) -> result on ks==0 lanes
            float accf[4][4];
            #pragma unroll
            for (int bi = 0; bi < 4; ++bi)
                #pragma unroll
                for (int g = 0; g < 4; ++g) {
                    const float2 v = unpk2(acc2[bi][g]);
                    float a = v.x + v.y;
                    a += __shfl_xor_sync(0xffffffffu, a, 1);
                    a += __shfl_xor_sync(0xffffffffu, a, 2);
                    a += __shfl_xor_sync(0xffffffffu, a, 4);
                    accf[bi][g] = a;
                }

            if (epi) {
                #pragma unroll
                for (int bi = 0; bi < 4; ++bi) {
                    const int b = pass * 4 + bi;
                    const float zi = accf[bi][0] + xv[b][0];
                    const float zf = accf[bi][1] + xv[b][1];
                    const float zg = accf[bi][2] + xv[b][2];
                    const float zo = accf[bi][3] + xv[b][3];
                    const float ig = sigf(zi), fg = sigf(zf), gg = tanh_f(zg), og = sigf(zo);
                    cc[b] = fg * cc[b] + ig * gg;
                    const float hval = og * tanh_f(cc[b]);
                    stage[b * 32 + ul] = hval;
                    hout[((size_t)t * BQ + b0 + b) * 512 + dof + u0 + ul] = hval;
                }
            }
        }

        __syncthreads();
        // push this CTA's slice into hbuf[1-p] of ALL 8 cluster CTAs (incl. self)
        {
            const float val = stage[tid];
            const uint32_t vb = __float_as_uint(val);
            const int b = tid >> 5, uu = tid & 31;
            const uint32_t loff = hb_addr + (uint32_t)((((1 - p) * 8 + b) * 256 + u0 + uu) * 4);
            #pragma unroll
            for (int peer = 0; peer < CLSZ; ++peer) {
                uint32_t raddr;
                asm("mapa.shared::cluster.u32 %0, %1, %2;" : "=r"(raddr) : "r"(loff), "r"(peer));
                asm volatile("st.shared::cluster.b32 [%0], %1;" :: "r"(raddr), "r"(vb) : "memory");
            }
        }
        asm volatile("barrier.cluster.arrive.aligned;" ::: "memory");
        asm volatile("barrier.cluster.wait.aligned;" ::: "memory");
        p ^= 1;
    }
}

// ---------------- CRF: one block per batch ----------------
__global__ void __launch_bounds__(64)
crf_kernel(const int* __restrict__ text, const int* __restrict__ sbj,
           const float* __restrict__ em, const float* __restrict__ start_t,
           const float* __restrict__ end_t, const float* __restrict__ trans,
           float* __restrict__ llh)
{
    const int b   = blockIdx.x;
    const int tid = threadIdx.x;
    __shared__ float tr[KQ * KQ];
    __shared__ float sc[KQ];
    for (int i = tid; i < KQ * KQ; i += 64) tr[i] = trans[i];
    if (tid < KQ) sc[tid] = start_t[tid] + em[(size_t)b * KQ + tid];
    __syncthreads();

    for (int t = 1; t < TQ; ++t) {
        const int tok = text[b * TQ + t];
        if (tok != 0) {
            float nv = 0.0f;
            if (tid < KQ) {
                float mx = -1e30f;
                #pragma unroll 1
                for (int j = 0; j < KQ; ++j) mx = fmaxf(mx, sc[j] + tr[j * KQ + tid]);
                float ssum = 0.0f;
                #pragma unroll 1
                for (int j = 0; j < KQ; ++j) ssum += __expf(sc[j] + tr[j * KQ + tid] - mx);
                nv = em[((size_t)t * BQ + b) * KQ + tid] + mx + __logf(ssum);
            }
            __syncthreads();
            if (tid < KQ) sc[tid] = nv;
            __syncthreads();
        }
    }

    if (tid == 0) {
        float mx = -1e30f;
        for (int k = 0; k < KQ; ++k) mx = fmaxf(mx, sc[k] + end_t[k]);
        float ssum = 0.0f;
        for (int k = 0; k < KQ; ++k) ssum += __expf(sc[k] + end_t[k] - mx);
        const float logZ = mx + __logf(ssum);
        int tag0 = sbj[b * TQ + 0];
        float num = start_t[tag0] + em[(size_t)b * KQ + tag0];
        int prev = tag0, last = tag0;
        for (int t = 1; t < TQ; ++t) {
            if (text[b * TQ + t] != 0) {
                const int tg = sbj[b * TQ + t];
                num += em[((size_t)t * BQ + b) * KQ + tg] + tr[prev * KQ + tg];
                prev = tg; last = tg;
            }
        }
        num += end_t[last];
        llh[b] = num - logZ;
    }
}

// ---------------- finalize ----------------
__global__ void __launch_bounds__(256)
finalize_kernel(const int* __restrict__ text, const float* __restrict__ llh,
                float* __restrict__ out)
{
    __shared__ float sred[256];
    __shared__ float cred[256];
    const int tid = threadIdx.x;
    float s = 0.0f, c = 0.0f;
    for (int i = tid; i < BQ; i += 256) s += llh[i];
    for (int i = tid; i < BQ * TQ; i += 256) c += (text[i] != 0) ? 1.0f : 0.0f;
    sred[tid] = s; cred[tid] = c;
    __syncthreads();
    for (int off = 128; off > 0; off >>= 1) {
        if (tid < off) { sred[tid] += sred[tid + off]; cred[tid] += cred[tid + off]; }
        __syncthreads();
    }
    if (tid == 0) out[0] = -(sred[0] / cred[0]);
}

// ---------------- launch ----------------
extern "C" void kernel_launch(void* const* d_in, const int* in_sizes, int n_in,
                              void* d_out, int out_size)
{
    const int*   text  = (const int*)  d_in[0];
    const int*   sbj   = (const int*)  d_in[1];
    const float* emb   = (const float*)d_in[2];
    const float* Wih0f = (const float*)d_in[3];
    const float* Whh0f = (const float*)d_in[4];
    const float* b0f   = (const float*)d_in[5];
    const float* Wih0b = (const float*)d_in[6];
    const float* Whh0b = (const float*)d_in[7];
    const float* b0b   = (const float*)d_in[8];
    const float* Wih1f = (const float*)d_in[9];
    const float* Whh1f = (const float*)d_in[10];
    const float* b1f   = (const float*)d_in[11];
    const float* Wih1b = (const float*)d_in[12];
    const float* Whh1b = (const float*)d_in[13];
    const float* b1b   = (const float*)d_in[14];
    const float* W_sbj = (const float*)d_in[15];
    const float* b_sbj = (const float*)d_in[16];
    const float* st_t  = (const float*)d_in[17];
    const float* en_t  = (const float*)d_in[18];
    const float* trans = (const float*)d_in[19];
    float* out = (float*)d_out;

    float *xgA, *xgB, *h0, *h1, *em, *llh;
    cudaGetSymbolAddress((void**)&xgA, g_xgA);
    cudaGetSymbolAddress((void**)&xgB, g_xgB);
    cudaGetSymbolAddress((void**)&h0,  g_h0);
    cudaGetSymbolAddress((void**)&h1,  g_h1);
    cudaGetSymbolAddress((void**)&em,  g_em);
    cudaGetSymbolAddress((void**)&llh, g_llh);

    const dim3 gGemmFull(1024 / GBN, MBQ / GBM);   // (8, 128)
    const dim3 gGemmEm(1, MBQ / GBM);              // (1, 128)  N=37

    gemm_nt_bias<true><<<gGemmFull, 256>>>(emb, text, Wih0f, b0f, xgA, MBQ, 1024, DQ, DQ);
    gemm_nt_bias<true><<<gGemmFull, 256>>>(emb, text, Wih0b, b0b, xgB, MBQ, 1024, DQ, DQ);
    lstm_scan_cluster<<<128, 256>>>(xgA, xgB, Whh0f, Whh0b, h0);

    gemm_nt_bias<false><<<gGemmFull, 256>>>(h0, nullptr, Wih1f, b1f, xgA, MBQ, 1024, 512, 512);
    gemm_nt_bias<false><<<gGemmFull, 256>>>(h0, nullptr, Wih1b, b1b, xgB, MBQ, 1024, 512, 512);
    lstm_scan_cluster<<<128, 256>>>(xgA, xgB, Whh1f, Whh1b, h1);

    gemm_nt_bias<false><<<gGemmEm, 256>>>(h1, nullptr, W_sbj, b_sbj, em, MBQ, KQ, 512, 512);

    crf_kernel<<<BQ, 64>>>(text, sbj, em, st_t, en_t, trans, llh);
    finalize_kernel<<<1, 256>>>(text, llh, out);
}